// round 10
// baseline (speedup 1.0000x reference)
#include <cuda_runtime.h>
#include <cuda_bf16.h>
#include <math.h>
#include <stdint.h>

#define D 128
static constexpr int MAXN = 51200;
static constexpr int MAXE = 1 << 20;
static constexpr int MAXMATS = 16;   // slots; last used slot holds Wg frags

// ---------------------------------------------------------------------------
// Scratch (no allocs allowed -> device globals)
// ---------------------------------------------------------------------------
__device__ float d_mj[MAXN * D];
__device__ float d_v [MAXN * D];
__device__ __align__(16) uint32_t d_wimg[MAXMATS * 16384];
// edge sort scratch
__device__ int d_cnt [MAXN];
__device__ int d_off [MAXN];
__device__ int d_bsum[256];
__device__ int d_perm[MAXE];
__device__ int d_is  [MAXE];
__device__ int d_js  [MAXE];

__device__ __forceinline__ float sspf(float x) {
    return fmaxf(x, 0.0f) + __logf(1.0f + __expf(-fabsf(x))) - 0.69314718055994530942f;
}

// ---------------------------------------------------------------------------
// HMMA m16n8k16 bf16 (base PTX) + frag building
// ---------------------------------------------------------------------------
__device__ __forceinline__ void mma_bf16(float* d, const uint32_t* a,
                                         uint32_t b0, uint32_t b1) {
    asm volatile(
        "mma.sync.aligned.m16n8k16.row.col.f32.bf16.bf16.f32 "
        "{%0,%1,%2,%3}, {%4,%5,%6,%7}, {%8,%9}, {%0,%1,%2,%3};"
        : "+f"(d[0]), "+f"(d[1]), "+f"(d[2]), "+f"(d[3])
        : "r"(a[0]), "r"(a[1]), "r"(a[2]), "r"(a[3]), "r"(b0), "r"(b1));
}

__device__ __forceinline__ void build_frag(float s0, float s1,
                                           uint32_t& hi, uint32_t& lo) {
    __nv_bfloat162 h2 = __floats2bfloat162_rn(s0, s1);
    float l0 = s0 - __bfloat162float(h2.x);
    float l1 = s1 - __bfloat162float(h2.y);
    __nv_bfloat162 l2 = __floats2bfloat162_rn(l0, l1);
    hi = *reinterpret_cast<uint32_t*>(&h2);
    lo = *reinterpret_cast<uint32_t*>(&l2);
}

// ---------------------------------------------------------------------------
// Weight precompute (8 blocks per matrix)
// ---------------------------------------------------------------------------
__global__ void wsplit_kernel(const float* __restrict__ Wj,
                              const float* __restrict__ Wi,
                              const float* __restrict__ Wf,
                              const float* __restrict__ rWint,
                              const float* __restrict__ rWatm,
                              const float* __restrict__ rWout,
                              const float* __restrict__ Wg,
                              int n_int, int n_atom, int n_out) {
    int m    = blockIdx.x >> 3;
    int part = blockIdx.x & 7;
    int n_mats = 3 + n_int + n_atom + n_out;

    if (m == n_mats) {  // Wg [32 x 128]
        uint32_t* hi = d_wimg + (size_t)m * 16384;
        uint32_t* lo = hi + 2048;
        for (int idx = part * 256 + threadIdx.x; idx < 2048; idx += 2048) {
            int ri = idx & 1;
            int l  = (idx >> 1) & 31;
            int f  = idx >> 6;
            int kt = f & 1, nt = f >> 1;
            int n  = nt * 8 + (l >> 2);
            int k0 = kt * 16 + 2 * (l & 3) + ri * 8;
            uint32_t h, lw;
            build_frag(Wg[k0 * D + n], Wg[(k0 + 1) * D + n], h, lw);
            hi[idx] = h;
            lo[idx] = lw;
        }
        return;
    }

    const float* src;
    if (m == 0)                      src = Wj;
    else if (m == 1)                 src = Wi;
    else if (m == 2)                 src = Wf;
    else if (m < 3 + n_int)          src = rWint + (size_t)(m - 3) * D * D;
    else if (m < 3 + n_int + n_atom) src = rWatm + (size_t)(m - 3 - n_int) * D * D;
    else                             src = rWout + (size_t)(m - 3 - n_int - n_atom) * D * D;

    uint32_t* hi = d_wimg + (size_t)m * 16384;
    uint32_t* lo = hi + 8192;

    for (int idx = part * 1024 + threadIdx.x; idx < (part + 1) * 1024; idx += 256) {
        int ri = idx & 1;
        int l  = (idx >> 1) & 31;
        int f  = idx >> 6;
        int kt = f & 7, nt = f >> 3;
        int n  = nt * 8 + (l >> 2);
        int k0 = kt * 16 + 2 * (l & 3) + ri * 8;
        uint32_t h, lw;
        build_frag(src[k0 * D + n], src[(k0 + 1) * D + n], h, lw);
        hi[idx] = h;
        lo[idx] = lw;
    }
}

// ---------------------------------------------------------------------------
// MMA stage with B in smem (head kernel)
// ---------------------------------------------------------------------------
__device__ __forceinline__ void stage_mma_smem(const uint32_t* wsm, int loff,
                                               const uint32_t* ahi, const uint32_t* alo,
                                               float* acc) {
    const char* base = reinterpret_cast<const char*>(wsm);
    #pragma unroll
    for (int kt = 0; kt < 8; kt++) {
        #pragma unroll
        for (int c = 0; c < 4; c++) {
            uint2 bh[4], bl[4];
            #pragma unroll
            for (int i = 0; i < 4; i++)
                bh[i] = *reinterpret_cast<const uint2*>(base + ((c * 4 + i) * 8 + kt) * 256 + loff);
            #pragma unroll
            for (int i = 0; i < 4; i++)
                bl[i] = *reinterpret_cast<const uint2*>(base + 32768 + ((c * 4 + i) * 8 + kt) * 256 + loff);
            #pragma unroll
            for (int i = 0; i < 4; i++)
                mma_bf16(acc + (c * 4 + i) * 4, ahi + kt * 4, bh[i].x, bh[i].y);
            #pragma unroll
            for (int i = 0; i < 4; i++)
                mma_bf16(acc + (c * 4 + i) * 4, alo + kt * 4, bh[i].x, bh[i].y);
            #pragma unroll
            for (int i = 0; i < 4; i++)
                mma_bf16(acc + (c * 4 + i) * 4, ahi + kt * 4, bl[i].x, bl[i].y);
        }
    }
}

// ---------------------------------------------------------------------------
// MMA stage with B via __ldg (tail kernel; weight image is L1-resident)
// ---------------------------------------------------------------------------
__device__ __forceinline__ void stage_mma_ldg(const uint32_t* __restrict__ img,
                                              int loff,
                                              const uint32_t* ahi, const uint32_t* alo,
                                              float* acc) {
    const char* base = reinterpret_cast<const char*>(img);
    #pragma unroll
    for (int kt = 0; kt < 8; kt++) {
        #pragma unroll
        for (int c = 0; c < 4; c++) {
            uint2 bh[4], bl[4];
            #pragma unroll
            for (int i = 0; i < 4; i++)
                bh[i] = __ldg(reinterpret_cast<const uint2*>(
                    base + ((c * 4 + i) * 8 + kt) * 256 + loff));
            #pragma unroll
            for (int i = 0; i < 4; i++)
                bl[i] = __ldg(reinterpret_cast<const uint2*>(
                    base + 32768 + ((c * 4 + i) * 8 + kt) * 256 + loff));
            #pragma unroll
            for (int i = 0; i < 4; i++)
                mma_bf16(acc + (c * 4 + i) * 4, ahi + kt * 4, bh[i].x, bh[i].y);
            #pragma unroll
            for (int i = 0; i < 4; i++)
                mma_bf16(acc + (c * 4 + i) * 4, alo + kt * 4, bh[i].x, bh[i].y);
            #pragma unroll
            for (int i = 0; i < 4; i++)
                mma_bf16(acc + (c * 4 + i) * 4, ahi + kt * 4, bl[i].x, bl[i].y);
        }
    }
}

// ---------------------------------------------------------------------------
// Head kernel: A = ssp(x); mj = ssp(A@Wj+bj); v = ssp(A@Wi+bi)
// ---------------------------------------------------------------------------
static constexpr int HEAD_SMEM = (16384 + 128) * 4;

__global__ void __launch_bounds__(256, 1)
tc_head_kernel(const float* __restrict__ x,
               const float* __restrict__ bj, const float* __restrict__ bi,
               float* __restrict__ mj, float* __restrict__ v, int N) {
    extern __shared__ uint32_t sm[];
    float* bias_s = reinterpret_cast<float*>(sm + 16384);

    const int t = threadIdx.x, w = t >> 5, l = t & 31;
    const int g = l >> 2, m4 = l & 3;
    const int loff = l * 8;
    const int row_lo = blockIdx.x * 128 + w * 16 + g;
    const int row_hi = row_lo + 8;
    const int cb = 2 * m4;

    uint32_t ahi[32], alo[32];
    #pragma unroll
    for (int nt = 0; nt < 16; nt++) {
        int c0 = nt * 8 + cb;
        float2 a = (row_lo < N) ? *reinterpret_cast<const float2*>(x + (size_t)row_lo * D + c0)
                                : make_float2(0.f, 0.f);
        float2 b = (row_hi < N) ? *reinterpret_cast<const float2*>(x + (size_t)row_hi * D + c0)
                                : make_float2(0.f, 0.f);
        int base = (nt >> 1) * 4 + (nt & 1) * 2;
        build_frag(sspf(a.x), sspf(a.y), ahi[base], alo[base]);
        build_frag(sspf(b.x), sspf(b.y), ahi[base + 1], alo[base + 1]);
    }

    for (int s = 0; s < 2; s++) {
        __syncthreads();
        const uint4* src = reinterpret_cast<const uint4*>(d_wimg + (size_t)s * 16384);
        uint4* dst = reinterpret_cast<uint4*>(sm);
        #pragma unroll
        for (int i = 0; i < 16; i++)
            dst[t + 256 * i] = src[t + 256 * i];
        if (t < 32)
            reinterpret_cast<float4*>(bias_s)[t] =
                reinterpret_cast<const float4*>(s ? bi : bj)[t];
        __syncthreads();

        float acc[64];
        #pragma unroll
        for (int i = 0; i < 64; i++) acc[i] = 0.0f;
        stage_mma_smem(sm, loff, ahi, alo, acc);

        float* outp = s ? v : mj;
        #pragma unroll
        for (int nt = 0; nt < 16; nt++) {
            int c0 = nt * 8 + cb;
            float bv0 = bias_s[c0], bv1 = bias_s[c0 + 1];
            float s0 = sspf(acc[nt * 4 + 0] + bv0);
            float s1 = sspf(acc[nt * 4 + 1] + bv1);
            float s2 = sspf(acc[nt * 4 + 2] + bv0);
            float s3 = sspf(acc[nt * 4 + 3] + bv1);
            if (row_lo < N)
                *reinterpret_cast<float2*>(outp + (size_t)row_lo * D + c0) = make_float2(s0, s1);
            if (row_hi < N)
                *reinterpret_cast<float2*>(outp + (size_t)row_hi * D + c0) = make_float2(s2, s3);
        }
    }
}

// ---------------------------------------------------------------------------
// Tail kernel: register-chained stages; weights via __ldg; NO barriers —
// warps skew freely so one warp's HMMA overlaps another's MUFU epilogue.
// ---------------------------------------------------------------------------
__global__ void __launch_bounds__(256, 1)
tc_tail_kernel(const float* __restrict__ v_in, const float* __restrict__ x,
               const float* __restrict__ u,
               const float* __restrict__ rbint, const float* __restrict__ bf,
               const float* __restrict__ rbatm, const float* __restrict__ rbout,
               int n_int, int n_atom, int n_out,
               float* __restrict__ h_out, float* __restrict__ o_out, int N) {
    const int t = threadIdx.x, w = t >> 5, l = t & 31;
    const int g = l >> 2, m4 = l & 3;
    const int loff = l * 8;
    const int row_lo = blockIdx.x * 128 + w * 16 + g;
    const int row_hi = row_lo + 8;
    const int cb = 2 * m4;

    const int total = 2 * n_int + 1 + 2 * n_atom + 2 * n_out;

    auto stage_desc = [&](int s, int& mat, const float*& bias, int& mode, bool& storeh) {
        storeh = false;
        if (s < 2 * n_int) {
            mat = 3 + (s >> 1); bias = rbint + (size_t)(s >> 1) * D;
            mode = (s & 1) ? 1 : 0;
        } else if (s == 2 * n_int) {
            mat = 2; bias = bf; mode = 2; storeh = (n_atom == 0);
        } else {
            int s2 = s - 2 * n_int - 1;
            if (s2 < 2 * n_atom) {
                mat = 3 + n_int + (s2 >> 1); bias = rbatm + (size_t)(s2 >> 1) * D;
                mode = (s2 & 1) ? 1 : 0;
                storeh = (s2 == 2 * n_atom - 1);
            } else {
                int s3 = s2 - 2 * n_atom;
                mat = 3 + n_int + n_atom + (s3 >> 1); bias = rbout + (size_t)(s3 >> 1) * D;
                mode = (s3 & 1) ? ((s3 == 2 * n_out - 1) ? 3 : 1) : 0;
            }
        }
    };

    float vr[64];
    uint32_t ahi[32], alo[32];
    #pragma unroll
    for (int nt = 0; nt < 16; nt++) {
        int c0 = nt * 8 + cb;
        float2 a = (row_lo < N) ? *reinterpret_cast<const float2*>(v_in + (size_t)row_lo * D + c0)
                                : make_float2(0.f, 0.f);
        float2 b = (row_hi < N) ? *reinterpret_cast<const float2*>(v_in + (size_t)row_hi * D + c0)
                                : make_float2(0.f, 0.f);
        vr[nt * 4 + 0] = a.x; vr[nt * 4 + 1] = a.y;
        vr[nt * 4 + 2] = b.x; vr[nt * 4 + 3] = b.y;
        int base = (nt >> 1) * 4 + (nt & 1) * 2;
        build_frag(sspf(a.x), sspf(a.y), ahi[base], alo[base]);
        build_frag(sspf(b.x), sspf(b.y), ahi[base + 1], alo[base + 1]);
    }

    for (int s = 0; s < total; s++) {
        int mat; const float* bias; int mode; bool storeh;
        stage_desc(s, mat, bias, mode, storeh);
        const uint32_t* img = d_wimg + (size_t)mat * 16384;

        float acc[64];
        #pragma unroll
        for (int i = 0; i < 64; i++) acc[i] = 0.0f;
        stage_mma_ldg(img, loff, ahi, alo, acc);

        #pragma unroll
        for (int nt = 0; nt < 16; nt++) {
            int c0 = nt * 8 + cb;
            float2 bv = __ldg(reinterpret_cast<const float2*>(bias + c0));
            float v0 = acc[nt * 4 + 0] + bv.x;
            float v1 = acc[nt * 4 + 1] + bv.y;
            float v2 = acc[nt * 4 + 2] + bv.x;
            float v3 = acc[nt * 4 + 3] + bv.y;
            if (mode == 1 || mode == 3) {
                v0 += vr[nt * 4 + 0]; v1 += vr[nt * 4 + 1];
                v2 += vr[nt * 4 + 2]; v3 += vr[nt * 4 + 3];
            }
            if (mode == 2) {
                float2 xl = (row_lo < N) ? *reinterpret_cast<const float2*>(x + (size_t)row_lo * D + c0)
                                         : make_float2(0.f, 0.f);
                float2 xh = (row_hi < N) ? *reinterpret_cast<const float2*>(x + (size_t)row_hi * D + c0)
                                         : make_float2(0.f, 0.f);
                float2 uv = __ldg(reinterpret_cast<const float2*>(u + c0));
                v0 += uv.x * sspf(xl.x); v1 += uv.y * sspf(xl.y);
                v2 += uv.x * sspf(xh.x); v3 += uv.y * sspf(xh.y);
            }
            if (mode == 1 || mode == 2) {
                vr[nt * 4 + 0] = v0; vr[nt * 4 + 1] = v1;
                vr[nt * 4 + 2] = v2; vr[nt * 4 + 3] = v3;
            }
            float s0 = sspf(v0), s1 = sspf(v1), s2 = sspf(v2), s3 = sspf(v3);
            if (mode == 3) {
                if (row_lo < N)
                    *reinterpret_cast<float2*>(o_out + (size_t)row_lo * D + c0) = make_float2(s0, s1);
                if (row_hi < N)
                    *reinterpret_cast<float2*>(o_out + (size_t)row_hi * D + c0) = make_float2(s2, s3);
            } else {
                int base = (nt >> 1) * 4 + (nt & 1) * 2;
                build_frag(s0, s1, ahi[base], alo[base]);
                build_frag(s2, s3, ahi[base + 1], alo[base + 1]);
            }
        }

        if (storeh) {
            #pragma unroll
            for (int nt = 0; nt < 16; nt++) {
                int c0 = nt * 8 + cb;
                if (row_lo < N)
                    *reinterpret_cast<float2*>(h_out + (size_t)row_lo * D + c0) =
                        make_float2(vr[nt * 4 + 0], vr[nt * 4 + 1]);
                if (row_hi < N)
                    *reinterpret_cast<float2*>(h_out + (size_t)row_hi * D + c0) =
                        make_float2(vr[nt * 4 + 2], vr[nt * 4 + 3]);
            }
        }
    }
}

// ---------------------------------------------------------------------------
// Edge sort: counting sort by idx_i (hierarchical scan)
// ---------------------------------------------------------------------------
__global__ void zero_kernel(int n) {
    int i = blockIdx.x * blockDim.x + threadIdx.x;
    if (i < n) d_cnt[i] = 0;
}

__global__ void hist_kernel(const int* __restrict__ idx_i, int E) {
    int e = blockIdx.x * blockDim.x + threadIdx.x;
    if (e < E) atomicAdd(&d_cnt[idx_i[e]], 1);
}

// per-256-block exclusive scan; block totals to d_bsum
__global__ void scan1_kernel(int n) {
    __shared__ int ws[8];
    const int t = threadIdx.x, l = t & 31, w = t >> 5;
    int i = blockIdx.x * 256 + t;
    int x = (i < n) ? d_cnt[i] : 0;
    int incl = x;
    #pragma unroll
    for (int s = 1; s < 32; s <<= 1) {
        int y = __shfl_up_sync(0xffffffffu, incl, s);
        if (l >= s) incl += y;
    }
    if (l == 31) ws[w] = incl;
    __syncthreads();
    if (t == 0) {
        int run = 0;
        #pragma unroll
        for (int k = 0; k < 8; k++) { int v = ws[k]; ws[k] = run; run += v; }
        d_bsum[blockIdx.x] = run;
    }
    __syncthreads();
    if (i < n) d_off[i] = ws[w] + incl - x;
}

// single-block exclusive scan of <=256 block sums (in place)
__global__ void scan2_kernel(int nb) {
    __shared__ int ws[8];
    const int t = threadIdx.x, l = t & 31, w = t >> 5;
    int x = (t < nb) ? d_bsum[t] : 0;
    int incl = x;
    #pragma unroll
    for (int s = 1; s < 32; s <<= 1) {
        int y = __shfl_up_sync(0xffffffffu, incl, s);
        if (l >= s) incl += y;
    }
    if (l == 31) ws[w] = incl;
    __syncthreads();
    if (t == 0) {
        int run = 0;
        #pragma unroll
        for (int k = 0; k < 8; k++) { int v = ws[k]; ws[k] = run; run += v; }
    }
    __syncthreads();
    if (t < nb) d_bsum[t] = ws[w] + incl - x;
}

__global__ void scan3_kernel(int n) {
    int i = blockIdx.x * 256 + threadIdx.x;
    if (i < n) d_off[i] += d_bsum[blockIdx.x];
}

__global__ void scatter_kernel(const int* __restrict__ idx_i,
                               const int* __restrict__ idx_j, int E) {
    int e = blockIdx.x * blockDim.x + threadIdx.x;
    if (e < E) {
        int i = idx_i[e];
        int pos = atomicAdd(&d_off[i], 1);
        d_perm[pos] = e;
        d_is[pos]   = i;
        d_js[pos]   = idx_j[e];
    }
}

// ---------------------------------------------------------------------------
// Edge kernel (sorted): HMMA gate, smem staging, run-aggregated red.v4.
// ---------------------------------------------------------------------------
static constexpr int EDGE_SMEM = (4096 + 4 * 16 * 132) * 4;

__global__ void __launch_bounds__(128)
edge_sorted_kernel(const float* __restrict__ g,
                   const float* __restrict__ mj,
                   float* __restrict__ v,
                   int E, int wg_slot) {
    extern __shared__ uint32_t esm[];
    uint32_t* wgs = esm;
    float* stag_all = reinterpret_cast<float*>(esm + 4096);

    {
        const uint4* src = reinterpret_cast<const uint4*>(d_wimg + (size_t)wg_slot * 16384);
        uint4* dst = reinterpret_cast<uint4*>(wgs);
        for (int i = threadIdx.x; i < 1024; i += 128)
            dst[i] = src[i];
    }
    __syncthreads();

    const int t = threadIdx.x, l = t & 31, w = t >> 5;
    const int gq = l >> 2, m4 = l & 3;
    const int p0 = (blockIdx.x * 4 + w) * 16;
    if (p0 >= E) return;
    const int bound = min(16, E - p0);

    float* stag = stag_all + w * 16 * 132;

    const bool v0ok = (gq < bound), v1ok = (8 + gq < bound);
    const int e0 = v0ok ? __ldg(d_perm + p0 + gq) : 0;
    const int j0 = v0ok ? __ldg(d_js + p0 + gq) : 0;
    const int e1 = v1ok ? __ldg(d_perm + p0 + 8 + gq) : 0;
    const int j1 = v1ok ? __ldg(d_js + p0 + 8 + gq) : 0;

    uint32_t ahi[8], alo[8];
    #pragma unroll
    for (int kt = 0; kt < 2; kt++) {
        int kb = kt * 16 + 2 * m4;
        float2 p00 = v0ok ? *reinterpret_cast<const float2*>(g + (size_t)e0 * 32 + kb)
                          : make_float2(0.f, 0.f);
        float2 p01 = v0ok ? *reinterpret_cast<const float2*>(g + (size_t)e0 * 32 + kb + 8)
                          : make_float2(0.f, 0.f);
        float2 p10 = v1ok ? *reinterpret_cast<const float2*>(g + (size_t)e1 * 32 + kb)
                          : make_float2(0.f, 0.f);
        float2 p11 = v1ok ? *reinterpret_cast<const float2*>(g + (size_t)e1 * 32 + kb + 8)
                          : make_float2(0.f, 0.f);
        build_frag(p00.x, p00.y, ahi[kt * 4 + 0], alo[kt * 4 + 0]);
        build_frag(p10.x, p10.y, ahi[kt * 4 + 1], alo[kt * 4 + 1]);
        build_frag(p01.x, p01.y, ahi[kt * 4 + 2], alo[kt * 4 + 2]);
        build_frag(p11.x, p11.y, ahi[kt * 4 + 3], alo[kt * 4 + 3]);
    }

    float acc[64];
    #pragma unroll
    for (int i = 0; i < 64; i++) acc[i] = 0.0f;

    const char* base = reinterpret_cast<const char*>(wgs);
    const int loff = l * 8;
    #pragma unroll
    for (int nt = 0; nt < 16; nt++) {
        #pragma unroll
        for (int kt = 0; kt < 2; kt++) {
            uint2 bh = *reinterpret_cast<const uint2*>(base + (nt * 2 + kt) * 256 + loff);
            mma_bf16(acc + nt * 4, ahi + kt * 4, bh.x, bh.y);
            mma_bf16(acc + nt * 4, alo + kt * 4, bh.x, bh.y);
            uint2 bl = *reinterpret_cast<const uint2*>(base + 8192 + (nt * 2 + kt) * 256 + loff);
            mma_bf16(acc + nt * 4, ahi + kt * 4, bl.x, bl.y);
        }
    }

    #pragma unroll
    for (int nt = 0; nt < 16; nt++) {
        int c0 = nt * 8 + 2 * m4;
        if (v0ok) {
            float2 m0 = *reinterpret_cast<const float2*>(mj + (size_t)j0 * D + c0);
            *reinterpret_cast<float2*>(stag + gq * 132 + c0) =
                make_float2(acc[nt * 4 + 0] * m0.x, acc[nt * 4 + 1] * m0.y);
        }
        if (v1ok) {
            float2 m1 = *reinterpret_cast<const float2*>(mj + (size_t)j1 * D + c0);
            *reinterpret_cast<float2*>(stag + (8 + gq) * 132 + c0) =
                make_float2(acc[nt * 4 + 2] * m1.x, acc[nt * 4 + 3] * m1.y);
        }
    }
    __syncwarp();

    int iv = (l < bound) ? __ldg(d_is + p0 + l) : -1;
    float4 s4 = *reinterpret_cast<const float4*>(stag + 0 * 132 + l * 4);
    int cur = __shfl_sync(0xffffffffu, iv, 0);
    for (int r = 1; r < bound; r++) {
        int ir = __shfl_sync(0xffffffffu, iv, r);
        float4 rv = *reinterpret_cast<const float4*>(stag + r * 132 + l * 4);
        if (ir == cur) {
            s4.x += rv.x; s4.y += rv.y; s4.z += rv.z; s4.w += rv.w;
        } else {
            asm volatile("red.global.add.v4.f32 [%0], {%1, %2, %3, %4};"
                         :: "l"(v + (size_t)cur * D + l * 4),
                            "f"(s4.x), "f"(s4.y), "f"(s4.z), "f"(s4.w) : "memory");
            s4 = rv; cur = ir;
        }
    }
    asm volatile("red.global.add.v4.f32 [%0], {%1, %2, %3, %4};"
                 :: "l"(v + (size_t)cur * D + l * 4),
                    "f"(s4.x), "f"(s4.y), "f"(s4.z), "f"(s4.w) : "memory");
}

// ---------------------------------------------------------------------------
// Host-side dispatch
// ---------------------------------------------------------------------------
extern "C" void kernel_launch(void* const* d_in, const int* in_sizes, int n_in,
                              void* d_out, int out_size) {
    const float* x     = (const float*)d_in[0];
    const float* g_ij  = (const float*)d_in[1];
    const float* Wf    = (const float*)d_in[2];
    const float* bf    = (const float*)d_in[3];
    const float* Wg    = (const float*)d_in[4];
    const float* Wj    = (const float*)d_in[5];
    const float* bj    = (const float*)d_in[6];
    const float* Wi    = (const float*)d_in[7];
    const float* bi    = (const float*)d_in[8];
    const float* u     = (const float*)d_in[9];
    const float* rWint = (const float*)d_in[10];
    const float* rbint = (const float*)d_in[11];
    const float* rWatm = (const float*)d_in[12];
    const float* rbatm = (const float*)d_in[13];
    const float* rWout = (const float*)d_in[14];
    const float* rbout = (const float*)d_in[15];
    const int*   idx_i = (const int*)d_in[16];
    const int*   idx_j = (const int*)d_in[17];

    const int N      = in_sizes[0] / D;
    const int E      = in_sizes[16];
    const int n_int  = in_sizes[11] / D;
    const int n_atom = in_sizes[13] / D;
    const int n_out  = in_sizes[15] / D;

    if (N > MAXN || E > MAXE) return;
    const int n_mats = 3 + n_int + n_atom + n_out;
    if (n_mats + 1 > MAXMATS) return;
    const int nblk = (N + 255) / 256;
    if (nblk > 256) return;

    float *mj, *v;
    cudaGetSymbolAddress((void**)&mj, d_mj);
    cudaGetSymbolAddress((void**)&v,  d_v);

    float* o_out = (float*)d_out;                 // o -> first N*D
    float* h_out = (float*)d_out + (size_t)N * D; // h -> second N*D

    cudaFuncSetAttribute(tc_head_kernel, cudaFuncAttributeMaxDynamicSharedMemorySize, HEAD_SMEM);
    cudaFuncSetAttribute(edge_sorted_kernel, cudaFuncAttributeMaxDynamicSharedMemorySize, EDGE_SMEM);

    const int tiles = (N + 127) / 128;

    // 0) split + permute weights (incl. Wg at slot n_mats)
    wsplit_kernel<<<(n_mats + 1) * 8, 256>>>(Wj, Wi, Wf, rWint, rWatm, rWout, Wg,
                                             n_int, n_atom, n_out);

    // 1) counting sort of edges by idx_i (hierarchical scan)
    zero_kernel<<<nblk, 256>>>(N);
    hist_kernel<<<(E + 255) / 256, 256>>>(idx_i, E);
    scan1_kernel<<<nblk, 256>>>(N);
    scan2_kernel<<<1, 256>>>(nblk);
    scan3_kernel<<<nblk, 256>>>(N);
    scatter_kernel<<<(E + 255) / 256, 256>>>(idx_i, idx_j, E);

    // 2) mj = ssp(ssp(x)@Wj+bj); v = ssp(ssp(x)@Wi+bi)
    tc_head_kernel<<<tiles, 256, HEAD_SMEM>>>(x, bj, bi, mj, v, N);

    // 3) v += segment_sum( (g_ij @ Wg) * mj[idx_j], idx_i )  [sorted + aggregated]
    {
        int batches = (E + 15) / 16;
        int blocks  = (batches + 3) / 4;
        edge_sorted_kernel<<<blocks, 128, EDGE_SMEM>>>(g_ij, mj, v, E, n_mats);
    }

    // 4) fused register-chained tail (barrier-free, LDG weights)
    tc_tail_kernel<<<tiles, 256>>>(
        v, x, u, rbint, bf, rbatm, rbout, n_int, n_atom, n_out, h_out, o_out, N);
}

// round 11
// speedup vs baseline: 1.2293x; 1.2293x over previous
#include <cuda_runtime.h>
#include <cuda_bf16.h>
#include <math.h>
#include <stdint.h>

#define D 128
static constexpr int MAXN = 51200;
static constexpr int MAXE = 1 << 20;
static constexpr int MAXMATS = 16;   // slots; last used slot holds Wg frags

// ---------------------------------------------------------------------------
// Scratch (no allocs allowed -> device globals)
// ---------------------------------------------------------------------------
__device__ float d_mj[MAXN * D];
__device__ float d_v [MAXN * D];
__device__ __align__(16) uint32_t d_wimg[MAXMATS * 16384];
// edge sort scratch
__device__ int d_cnt [MAXN];
__device__ int d_off [MAXN];
__device__ int d_bsum[256];
__device__ int d_perm[MAXE];
__device__ int d_is  [MAXE];
__device__ int d_js  [MAXE];

__device__ __forceinline__ float sspf(float x) {
    return fmaxf(x, 0.0f) + __logf(1.0f + __expf(-fabsf(x))) - 0.69314718055994530942f;
}

// ---------------------------------------------------------------------------
// HMMA m16n8k16 bf16 (base PTX) + frag building
// ---------------------------------------------------------------------------
__device__ __forceinline__ void mma_bf16(float* d, const uint32_t* a,
                                         uint32_t b0, uint32_t b1) {
    asm volatile(
        "mma.sync.aligned.m16n8k16.row.col.f32.bf16.bf16.f32 "
        "{%0,%1,%2,%3}, {%4,%5,%6,%7}, {%8,%9}, {%0,%1,%2,%3};"
        : "+f"(d[0]), "+f"(d[1]), "+f"(d[2]), "+f"(d[3])
        : "r"(a[0]), "r"(a[1]), "r"(a[2]), "r"(a[3]), "r"(b0), "r"(b1));
}

__device__ __forceinline__ void build_frag(float s0, float s1,
                                           uint32_t& hi, uint32_t& lo) {
    __nv_bfloat162 h2 = __floats2bfloat162_rn(s0, s1);
    float l0 = s0 - __bfloat162float(h2.x);
    float l1 = s1 - __bfloat162float(h2.y);
    __nv_bfloat162 l2 = __floats2bfloat162_rn(l0, l1);
    hi = *reinterpret_cast<uint32_t*>(&h2);
    lo = *reinterpret_cast<uint32_t*>(&l2);
}

// ---------------------------------------------------------------------------
// cp.async helpers
// ---------------------------------------------------------------------------
__device__ __forceinline__ uint32_t smem_u32(const void* p) {
    uint32_t a;
    asm("{ .reg .u64 t; cvta.to.shared.u64 t, %1; cvt.u32.u64 %0, t; }"
        : "=r"(a) : "l"(p));
    return a;
}
#define CP_ASYNC16(dst, src) \
    asm volatile("cp.async.cg.shared.global [%0], [%1], 16;" :: "r"(dst), "l"(src))
#define CP_COMMIT() asm volatile("cp.async.commit_group;" ::: "memory")
#define CP_WAIT1()  asm volatile("cp.async.wait_group 1;"  ::: "memory")

// ---------------------------------------------------------------------------
// Weight precompute (8 blocks per matrix)
// ---------------------------------------------------------------------------
__global__ void wsplit_kernel(const float* __restrict__ Wj,
                              const float* __restrict__ Wi,
                              const float* __restrict__ Wf,
                              const float* __restrict__ rWint,
                              const float* __restrict__ rWatm,
                              const float* __restrict__ rWout,
                              const float* __restrict__ Wg,
                              int n_int, int n_atom, int n_out) {
    int m    = blockIdx.x >> 3;
    int part = blockIdx.x & 7;
    int n_mats = 3 + n_int + n_atom + n_out;

    if (m == n_mats) {  // Wg [32 x 128]
        uint32_t* hi = d_wimg + (size_t)m * 16384;
        uint32_t* lo = hi + 2048;
        for (int idx = part * 256 + threadIdx.x; idx < 2048; idx += 2048) {
            int ri = idx & 1;
            int l  = (idx >> 1) & 31;
            int f  = idx >> 6;
            int kt = f & 1, nt = f >> 1;
            int n  = nt * 8 + (l >> 2);
            int k0 = kt * 16 + 2 * (l & 3) + ri * 8;
            uint32_t h, lw;
            build_frag(Wg[k0 * D + n], Wg[(k0 + 1) * D + n], h, lw);
            hi[idx] = h;
            lo[idx] = lw;
        }
        return;
    }

    const float* src;
    if (m == 0)                      src = Wj;
    else if (m == 1)                 src = Wi;
    else if (m == 2)                 src = Wf;
    else if (m < 3 + n_int)          src = rWint + (size_t)(m - 3) * D * D;
    else if (m < 3 + n_int + n_atom) src = rWatm + (size_t)(m - 3 - n_int) * D * D;
    else                             src = rWout + (size_t)(m - 3 - n_int - n_atom) * D * D;

    uint32_t* hi = d_wimg + (size_t)m * 16384;
    uint32_t* lo = hi + 8192;

    for (int idx = part * 1024 + threadIdx.x; idx < (part + 1) * 1024; idx += 256) {
        int ri = idx & 1;
        int l  = (idx >> 1) & 31;
        int f  = idx >> 6;
        int kt = f & 7, nt = f >> 3;
        int n  = nt * 8 + (l >> 2);
        int k0 = kt * 16 + 2 * (l & 3) + ri * 8;
        uint32_t h, lw;
        build_frag(src[k0 * D + n], src[(k0 + 1) * D + n], h, lw);
        hi[idx] = h;
        lo[idx] = lw;
    }
}

// ---------------------------------------------------------------------------
// MMA stage with B in smem: pass-separated, 4-nt register chunks.
// ---------------------------------------------------------------------------
__device__ __forceinline__ void stage_mma_smem(const uint32_t* wsm, int loff,
                                               const uint32_t* ahi, const uint32_t* alo,
                                               float* acc) {
    const char* base = reinterpret_cast<const char*>(wsm);
    #pragma unroll
    for (int kt = 0; kt < 8; kt++) {
        #pragma unroll
        for (int c = 0; c < 4; c++) {
            uint2 bh[4], bl[4];
            #pragma unroll
            for (int i = 0; i < 4; i++)
                bh[i] = *reinterpret_cast<const uint2*>(base + ((c * 4 + i) * 8 + kt) * 256 + loff);
            #pragma unroll
            for (int i = 0; i < 4; i++)
                bl[i] = *reinterpret_cast<const uint2*>(base + 32768 + ((c * 4 + i) * 8 + kt) * 256 + loff);
            #pragma unroll
            for (int i = 0; i < 4; i++)
                mma_bf16(acc + (c * 4 + i) * 4, ahi + kt * 4, bh[i].x, bh[i].y);
            #pragma unroll
            for (int i = 0; i < 4; i++)
                mma_bf16(acc + (c * 4 + i) * 4, alo + kt * 4, bh[i].x, bh[i].y);
            #pragma unroll
            for (int i = 0; i < 4; i++)
                mma_bf16(acc + (c * 4 + i) * 4, ahi + kt * 4, bl[i].x, bl[i].y);
        }
    }
}

// ---------------------------------------------------------------------------
// Head kernel: A = ssp(x); mj = ssp(A@Wj+bj); v = ssp(A@Wi+bi)
// ---------------------------------------------------------------------------
static constexpr int HEAD_SMEM = (16384 + 128) * 4;

__global__ void __launch_bounds__(256, 1)
tc_head_kernel(const float* __restrict__ x,
               const float* __restrict__ bj, const float* __restrict__ bi,
               float* __restrict__ mj, float* __restrict__ v, int N) {
    extern __shared__ uint32_t sm[];
    float* bias_s = reinterpret_cast<float*>(sm + 16384);

    const int t = threadIdx.x, w = t >> 5, l = t & 31;
    const int g = l >> 2, m4 = l & 3;
    const int loff = l * 8;
    const int row_lo = blockIdx.x * 128 + w * 16 + g;
    const int row_hi = row_lo + 8;
    const int cb = 2 * m4;

    uint32_t ahi[32], alo[32];
    #pragma unroll
    for (int nt = 0; nt < 16; nt++) {
        int c0 = nt * 8 + cb;
        float2 a = (row_lo < N) ? *reinterpret_cast<const float2*>(x + (size_t)row_lo * D + c0)
                                : make_float2(0.f, 0.f);
        float2 b = (row_hi < N) ? *reinterpret_cast<const float2*>(x + (size_t)row_hi * D + c0)
                                : make_float2(0.f, 0.f);
        int base = (nt >> 1) * 4 + (nt & 1) * 2;
        build_frag(sspf(a.x), sspf(a.y), ahi[base], alo[base]);
        build_frag(sspf(b.x), sspf(b.y), ahi[base + 1], alo[base + 1]);
    }

    for (int s = 0; s < 2; s++) {
        __syncthreads();
        const uint4* src = reinterpret_cast<const uint4*>(d_wimg + (size_t)s * 16384);
        uint4* dst = reinterpret_cast<uint4*>(sm);
        #pragma unroll
        for (int i = 0; i < 16; i++)
            dst[t + 256 * i] = src[t + 256 * i];
        if (t < 32)
            reinterpret_cast<float4*>(bias_s)[t] =
                reinterpret_cast<const float4*>(s ? bi : bj)[t];
        __syncthreads();

        float acc[64];
        #pragma unroll
        for (int i = 0; i < 64; i++) acc[i] = 0.0f;
        stage_mma_smem(sm, loff, ahi, alo, acc);

        float* outp = s ? v : mj;
        #pragma unroll
        for (int nt = 0; nt < 16; nt++) {
            int c0 = nt * 8 + cb;
            float bv0 = bias_s[c0], bv1 = bias_s[c0 + 1];
            float s0 = sspf(acc[nt * 4 + 0] + bv0);
            float s1 = sspf(acc[nt * 4 + 1] + bv1);
            float s2 = sspf(acc[nt * 4 + 2] + bv0);
            float s3 = sspf(acc[nt * 4 + 3] + bv1);
            if (row_lo < N)
                *reinterpret_cast<float2*>(outp + (size_t)row_lo * D + c0) = make_float2(s0, s1);
            if (row_hi < N)
                *reinterpret_cast<float2*>(outp + (size_t)row_hi * D + c0) = make_float2(s2, s3);
        }
    }
}

// ---------------------------------------------------------------------------
// Tail kernel (R6 proven design): register-chained, cp.async double-buffered
// ---------------------------------------------------------------------------
static constexpr int BUFW = 16512;
static constexpr int TAIL_SMEM = (2 * BUFW + 128) * 4;

__device__ __forceinline__ void issue_stage_copy(uint32_t buf_addr,
                                                 const uint32_t* img,
                                                 const float* bias, int t) {
    #pragma unroll
    for (int i = 0; i < 16; i++)
        CP_ASYNC16(buf_addr + (t + 256 * i) * 16, img + (t + 256 * i) * 4);
    if (t < 32)
        CP_ASYNC16(buf_addr + 16384 * 4 + t * 16, bias + t * 4);
}

__global__ void __launch_bounds__(256, 1)
tc_tail_kernel(const float* __restrict__ v_in, const float* __restrict__ x,
               const float* __restrict__ u,
               const float* __restrict__ rbint, const float* __restrict__ bf,
               const float* __restrict__ rbatm, const float* __restrict__ rbout,
               int n_int, int n_atom, int n_out,
               float* __restrict__ h_out, float* __restrict__ o_out, int N) {
    extern __shared__ uint32_t sm[];
    float* u_s = reinterpret_cast<float*>(sm + 2 * BUFW);
    const uint32_t sm_addr = smem_u32(sm);

    const int t = threadIdx.x, w = t >> 5, l = t & 31;
    const int g = l >> 2, m4 = l & 3;
    const int loff = l * 8;
    const int row_lo = blockIdx.x * 128 + w * 16 + g;
    const int row_hi = row_lo + 8;
    const int cb = 2 * m4;

    if (t < 32)
        reinterpret_cast<float4*>(u_s)[t] = reinterpret_cast<const float4*>(u)[t];

    const int total = 2 * n_int + 1 + 2 * n_atom + 2 * n_out;

    auto stage_desc = [&](int s, int& mat, const float*& bias, int& mode, bool& storeh) {
        storeh = false;
        if (s < 2 * n_int) {
            mat = 3 + (s >> 1); bias = rbint + (size_t)(s >> 1) * D;
            mode = (s & 1) ? 1 : 0;
        } else if (s == 2 * n_int) {
            mat = 2; bias = bf; mode = 2; storeh = (n_atom == 0);
        } else {
            int s2 = s - 2 * n_int - 1;
            if (s2 < 2 * n_atom) {
                mat = 3 + n_int + (s2 >> 1); bias = rbatm + (size_t)(s2 >> 1) * D;
                mode = (s2 & 1) ? 1 : 0;
                storeh = (s2 == 2 * n_atom - 1);
            } else {
                int s3 = s2 - 2 * n_atom;
                mat = 3 + n_int + n_atom + (s3 >> 1); bias = rbout + (size_t)(s3 >> 1) * D;
                mode = (s3 & 1) ? ((s3 == 2 * n_out - 1) ? 3 : 1) : 0;
            }
        }
    };

    {
        int mat; const float* bias; int mode; bool sh;
        stage_desc(0, mat, bias, mode, sh);
        issue_stage_copy(sm_addr, d_wimg + (size_t)mat * 16384, bias, t);
        CP_COMMIT();
    }

    float vr[64];
    uint32_t ahi[32], alo[32];
    #pragma unroll
    for (int nt = 0; nt < 16; nt++) {
        int c0 = nt * 8 + cb;
        float2 a = (row_lo < N) ? *reinterpret_cast<const float2*>(v_in + (size_t)row_lo * D + c0)
                                : make_float2(0.f, 0.f);
        float2 b = (row_hi < N) ? *reinterpret_cast<const float2*>(v_in + (size_t)row_hi * D + c0)
                                : make_float2(0.f, 0.f);
        vr[nt * 4 + 0] = a.x; vr[nt * 4 + 1] = a.y;
        vr[nt * 4 + 2] = b.x; vr[nt * 4 + 3] = b.y;
        int base = (nt >> 1) * 4 + (nt & 1) * 2;
        build_frag(sspf(a.x), sspf(a.y), ahi[base], alo[base]);
        build_frag(sspf(b.x), sspf(b.y), ahi[base + 1], alo[base + 1]);
    }

    for (int s = 0; s < total; s++) {
        int mat; const float* bias; int mode; bool storeh;
        stage_desc(s, mat, bias, mode, storeh);

        if (s + 1 < total) {
            int nmat; const float* nbias; int nmode; bool nsh;
            stage_desc(s + 1, nmat, nbias, nmode, nsh);
            issue_stage_copy(sm_addr + ((s + 1) & 1) * BUFW * 4,
                             d_wimg + (size_t)nmat * 16384, nbias, t);
        }
        CP_COMMIT();
        CP_WAIT1();
        __syncthreads();

        const uint32_t* wbuf = sm + (s & 1) * BUFW;
        const float* bias_s = reinterpret_cast<const float*>(wbuf + 16384);

        float acc[64];
        #pragma unroll
        for (int i = 0; i < 64; i++) acc[i] = 0.0f;
        stage_mma_smem(wbuf, loff, ahi, alo, acc);

        #pragma unroll
        for (int nt = 0; nt < 16; nt++) {
            int c0 = nt * 8 + cb;
            float bv0 = bias_s[c0], bv1 = bias_s[c0 + 1];
            float v0 = acc[nt * 4 + 0] + bv0;
            float v1 = acc[nt * 4 + 1] + bv1;
            float v2 = acc[nt * 4 + 2] + bv0;
            float v3 = acc[nt * 4 + 3] + bv1;
            if (mode == 1 || mode == 3) {
                v0 += vr[nt * 4 + 0]; v1 += vr[nt * 4 + 1];
                v2 += vr[nt * 4 + 2]; v3 += vr[nt * 4 + 3];
            }
            if (mode == 2) {
                float2 xl = (row_lo < N) ? *reinterpret_cast<const float2*>(x + (size_t)row_lo * D + c0)
                                         : make_float2(0.f, 0.f);
                float2 xh = (row_hi < N) ? *reinterpret_cast<const float2*>(x + (size_t)row_hi * D + c0)
                                         : make_float2(0.f, 0.f);
                float u0 = u_s[c0], u1 = u_s[c0 + 1];
                v0 += u0 * sspf(xl.x); v1 += u1 * sspf(xl.y);
                v2 += u0 * sspf(xh.x); v3 += u1 * sspf(xh.y);
            }
            if (mode == 1 || mode == 2) {
                vr[nt * 4 + 0] = v0; vr[nt * 4 + 1] = v1;
                vr[nt * 4 + 2] = v2; vr[nt * 4 + 3] = v3;
            }
            float s0 = sspf(v0), s1 = sspf(v1), s2 = sspf(v2), s3 = sspf(v3);
            if (mode == 3) {
                if (row_lo < N)
                    *reinterpret_cast<float2*>(o_out + (size_t)row_lo * D + c0) = make_float2(s0, s1);
                if (row_hi < N)
                    *reinterpret_cast<float2*>(o_out + (size_t)row_hi * D + c0) = make_float2(s2, s3);
            } else {
                int base = (nt >> 1) * 4 + (nt & 1) * 2;
                build_frag(s0, s1, ahi[base], alo[base]);
                build_frag(s2, s3, ahi[base + 1], alo[base + 1]);
            }
        }

        if (storeh) {
            #pragma unroll
            for (int nt = 0; nt < 16; nt++) {
                int c0 = nt * 8 + cb;
                if (row_lo < N)
                    *reinterpret_cast<float2*>(h_out + (size_t)row_lo * D + c0) =
                        make_float2(vr[nt * 4 + 0], vr[nt * 4 + 1]);
                if (row_hi < N)
                    *reinterpret_cast<float2*>(h_out + (size_t)row_hi * D + c0) =
                        make_float2(vr[nt * 4 + 2], vr[nt * 4 + 3]);
            }
        }
        __syncthreads();
    }
}

// ---------------------------------------------------------------------------
// Edge sort: counting sort by idx_i (hierarchical scan)
// ---------------------------------------------------------------------------
__global__ void zero_kernel(int n) {
    int i = blockIdx.x * blockDim.x + threadIdx.x;
    if (i < n) d_cnt[i] = 0;
}

__global__ void hist_kernel(const int* __restrict__ idx_i, int E) {
    int e = blockIdx.x * blockDim.x + threadIdx.x;
    if (e < E) atomicAdd(&d_cnt[idx_i[e]], 1);
}

__global__ void scan1_kernel(int n) {
    __shared__ int ws[8];
    const int t = threadIdx.x, l = t & 31, w = t >> 5;
    int i = blockIdx.x * 256 + t;
    int x = (i < n) ? d_cnt[i] : 0;
    int incl = x;
    #pragma unroll
    for (int s = 1; s < 32; s <<= 1) {
        int y = __shfl_up_sync(0xffffffffu, incl, s);
        if (l >= s) incl += y;
    }
    if (l == 31) ws[w] = incl;
    __syncthreads();
    if (t == 0) {
        int run = 0;
        #pragma unroll
        for (int k = 0; k < 8; k++) { int v = ws[k]; ws[k] = run; run += v; }
        d_bsum[blockIdx.x] = run;
    }
    __syncthreads();
    if (i < n) d_off[i] = ws[w] + incl - x;
}

__global__ void scan2_kernel(int nb) {
    __shared__ int ws[8];
    const int t = threadIdx.x, l = t & 31, w = t >> 5;
    int x = (t < nb) ? d_bsum[t] : 0;
    int incl = x;
    #pragma unroll
    for (int s = 1; s < 32; s <<= 1) {
        int y = __shfl_up_sync(0xffffffffu, incl, s);
        if (l >= s) incl += y;
    }
    if (l == 31) ws[w] = incl;
    __syncthreads();
    if (t == 0) {
        int run = 0;
        #pragma unroll
        for (int k = 0; k < 8; k++) { int v = ws[k]; ws[k] = run; run += v; }
    }
    __syncthreads();
    if (t < nb) d_bsum[t] = ws[w] + incl - x;
}

__global__ void scan3_kernel(int n) {
    int i = blockIdx.x * 256 + threadIdx.x;
    if (i < n) d_off[i] += d_bsum[blockIdx.x];
}

__global__ void scatter_kernel(const int* __restrict__ idx_i,
                               const int* __restrict__ idx_j, int E) {
    int e = blockIdx.x * blockDim.x + threadIdx.x;
    if (e < E) {
        int i = idx_i[e];
        int pos = atomicAdd(&d_off[i], 1);
        d_perm[pos] = e;
        d_is[pos]   = i;
        d_js[pos]   = idx_j[e];
    }
}

// ---------------------------------------------------------------------------
// Edge kernel (sorted): HMMA gate, smem staging, run-aggregated red.v4.
// 256 threads = 8 warps; warp handles 16 consecutive sorted edges.
// ---------------------------------------------------------------------------
static constexpr int EDGE_SMEM = (4096 + 8 * 16 * 132) * 4;   // 83968 B

__global__ void __launch_bounds__(256)
edge_sorted_kernel(const float* __restrict__ g,
                   const float* __restrict__ mj,
                   float* __restrict__ v,
                   int E, int wg_slot) {
    extern __shared__ uint32_t esm[];
    uint32_t* wgs = esm;
    float* stag_all = reinterpret_cast<float*>(esm + 4096);

    {
        const uint4* src = reinterpret_cast<const uint4*>(d_wimg + (size_t)wg_slot * 16384);
        uint4* dst = reinterpret_cast<uint4*>(wgs);
        for (int i = threadIdx.x; i < 1024; i += 256)
            dst[i] = src[i];
    }
    __syncthreads();

    const int t = threadIdx.x, l = t & 31, w = t >> 5;
    const int gq = l >> 2, m4 = l & 3;
    const int p0 = (blockIdx.x * 8 + w) * 16;
    if (p0 >= E) return;
    const int bound = min(16, E - p0);

    float* stag = stag_all + w * 16 * 132;

    const bool v0ok = (gq < bound), v1ok = (8 + gq < bound);
    const int e0 = v0ok ? __ldg(d_perm + p0 + gq) : 0;
    const int j0 = v0ok ? __ldg(d_js + p0 + gq) : 0;
    const int e1 = v1ok ? __ldg(d_perm + p0 + 8 + gq) : 0;
    const int j1 = v1ok ? __ldg(d_js + p0 + 8 + gq) : 0;

    uint32_t ahi[8], alo[8];
    #pragma unroll
    for (int kt = 0; kt < 2; kt++) {
        int kb = kt * 16 + 2 * m4;
        float2 p00 = v0ok ? *reinterpret_cast<const float2*>(g + (size_t)e0 * 32 + kb)
                          : make_float2(0.f, 0.f);
        float2 p01 = v0ok ? *reinterpret_cast<const float2*>(g + (size_t)e0 * 32 + kb + 8)
                          : make_float2(0.f, 0.f);
        float2 p10 = v1ok ? *reinterpret_cast<const float2*>(g + (size_t)e1 * 32 + kb)
                          : make_float2(0.f, 0.f);
        float2 p11 = v1ok ? *reinterpret_cast<const float2*>(g + (size_t)e1 * 32 + kb + 8)
                          : make_float2(0.f, 0.f);
        build_frag(p00.x, p00.y, ahi[kt * 4 + 0], alo[kt * 4 + 0]);
        build_frag(p10.x, p10.y, ahi[kt * 4 + 1], alo[kt * 4 + 1]);
        build_frag(p01.x, p01.y, ahi[kt * 4 + 2], alo[kt * 4 + 2]);
        build_frag(p11.x, p11.y, ahi[kt * 4 + 3], alo[kt * 4 + 3]);
    }

    float acc[64];
    #pragma unroll
    for (int i = 0; i < 64; i++) acc[i] = 0.0f;

    const char* base = reinterpret_cast<const char*>(wgs);
    const int loff = l * 8;
    #pragma unroll
    for (int nt = 0; nt < 16; nt++) {
        #pragma unroll
        for (int kt = 0; kt < 2; kt++) {
            uint2 bh = *reinterpret_cast<const uint2*>(base + (nt * 2 + kt) * 256 + loff);
            mma_bf16(acc + nt * 4, ahi + kt * 4, bh.x, bh.y);
            mma_bf16(acc + nt * 4, alo + kt * 4, bh.x, bh.y);
            uint2 bl = *reinterpret_cast<const uint2*>(base + 8192 + (nt * 2 + kt) * 256 + loff);
            mma_bf16(acc + nt * 4, ahi + kt * 4, bl.x, bl.y);
        }
    }

    #pragma unroll
    for (int nt = 0; nt < 16; nt++) {
        int c0 = nt * 8 + 2 * m4;
        if (v0ok) {
            float2 m0 = *reinterpret_cast<const float2*>(mj + (size_t)j0 * D + c0);
            *reinterpret_cast<float2*>(stag + gq * 132 + c0) =
                make_float2(acc[nt * 4 + 0] * m0.x, acc[nt * 4 + 1] * m0.y);
        }
        if (v1ok) {
            float2 m1 = *reinterpret_cast<const float2*>(mj + (size_t)j1 * D + c0);
            *reinterpret_cast<float2*>(stag + (8 + gq) * 132 + c0) =
                make_float2(acc[nt * 4 + 2] * m1.x, acc[nt * 4 + 3] * m1.y);
        }
    }
    __syncwarp();

    int iv = (l < bound) ? __ldg(d_is + p0 + l) : -1;
    float4 s4 = *reinterpret_cast<const float4*>(stag + 0 * 132 + l * 4);
    int cur = __shfl_sync(0xffffffffu, iv, 0);
    for (int r = 1; r < bound; r++) {
        int ir = __shfl_sync(0xffffffffu, iv, r);
        float4 rv = *reinterpret_cast<const float4*>(stag + r * 132 + l * 4);
        if (ir == cur) {
            s4.x += rv.x; s4.y += rv.y; s4.z += rv.z; s4.w += rv.w;
        } else {
            asm volatile("red.global.add.v4.f32 [%0], {%1, %2, %3, %4};"
                         :: "l"(v + (size_t)cur * D + l * 4),
                            "f"(s4.x), "f"(s4.y), "f"(s4.z), "f"(s4.w) : "memory");
            s4 = rv; cur = ir;
        }
    }
    asm volatile("red.global.add.v4.f32 [%0], {%1, %2, %3, %4};"
                 :: "l"(v + (size_t)cur * D + l * 4),
                    "f"(s4.x), "f"(s4.y), "f"(s4.z), "f"(s4.w) : "memory");
}

// ---------------------------------------------------------------------------
// Host-side dispatch
// ---------------------------------------------------------------------------
extern "C" void kernel_launch(void* const* d_in, const int* in_sizes, int n_in,
                              void* d_out, int out_size) {
    const float* x     = (const float*)d_in[0];
    const float* g_ij  = (const float*)d_in[1];
    const float* Wf    = (const float*)d_in[2];
    const float* bf    = (const float*)d_in[3];
    const float* Wg    = (const float*)d_in[4];
    const float* Wj    = (const float*)d_in[5];
    const float* bj    = (const float*)d_in[6];
    const float* Wi    = (const float*)d_in[7];
    const float* bi    = (const float*)d_in[8];
    const float* u     = (const float*)d_in[9];
    const float* rWint = (const float*)d_in[10];
    const float* rbint = (const float*)d_in[11];
    const float* rWatm = (const float*)d_in[12];
    const float* rbatm = (const float*)d_in[13];
    const float* rWout = (const float*)d_in[14];
    const float* rbout = (const float*)d_in[15];
    const int*   idx_i = (const int*)d_in[16];
    const int*   idx_j = (const int*)d_in[17];

    const int N      = in_sizes[0] / D;
    const int E      = in_sizes[16];
    const int n_int  = in_sizes[11] / D;
    const int n_atom = in_sizes[13] / D;
    const int n_out  = in_sizes[15] / D;

    if (N > MAXN || E > MAXE) return;
    const int n_mats = 3 + n_int + n_atom + n_out;
    if (n_mats + 1 > MAXMATS) return;
    const int nblk = (N + 255) / 256;
    if (nblk > 256) return;

    float *mj, *v;
    cudaGetSymbolAddress((void**)&mj, d_mj);
    cudaGetSymbolAddress((void**)&v,  d_v);

    float* o_out = (float*)d_out;                 // o -> first N*D
    float* h_out = (float*)d_out + (size_t)N * D; // h -> second N*D

    cudaFuncSetAttribute(tc_head_kernel, cudaFuncAttributeMaxDynamicSharedMemorySize, HEAD_SMEM);
    cudaFuncSetAttribute(tc_tail_kernel, cudaFuncAttributeMaxDynamicSharedMemorySize, TAIL_SMEM);
    cudaFuncSetAttribute(edge_sorted_kernel, cudaFuncAttributeMaxDynamicSharedMemorySize, EDGE_SMEM);

    const int tiles = (N + 127) / 128;

    // 0) split + permute weights (incl. Wg at slot n_mats)
    wsplit_kernel<<<(n_mats + 1) * 8, 256>>>(Wj, Wi, Wf, rWint, rWatm, rWout, Wg,
                                             n_int, n_atom, n_out);

    // 1) counting sort of edges by idx_i (hierarchical scan)
    zero_kernel<<<nblk, 256>>>(N);
    hist_kernel<<<(E + 255) / 256, 256>>>(idx_i, E);
    scan1_kernel<<<nblk, 256>>>(N);
    scan2_kernel<<<1, 256>>>(nblk);
    scan3_kernel<<<nblk, 256>>>(N);
    scatter_kernel<<<(E + 255) / 256, 256>>>(idx_i, idx_j, E);

    // 2) mj = ssp(ssp(x)@Wj+bj); v = ssp(ssp(x)@Wi+bi)
    tc_head_kernel<<<tiles, 256, HEAD_SMEM>>>(x, bj, bi, mj, v, N);

    // 3) v += segment_sum( (g_ij @ Wg) * mj[idx_j], idx_i )  [sorted + aggregated]
    {
        int batches = (E + 15) / 16;
        int blocks  = (batches + 7) / 8;
        edge_sorted_kernel<<<blocks, 256, EDGE_SMEM>>>(g_ij, mj, v, E, n_mats);
    }

    // 4) fused register-chained tail (R6 design)
    tc_tail_kernel<<<tiles, 256, TAIL_SMEM>>>(
        v, x, u, rbint, bf, rbatm, rbout, n_int, n_atom, n_out, h_out, o_out, N);
}